// round 17
// baseline (speedup 1.0000x reference)
#include <cuda_runtime.h>
#include <cuda_bf16.h>
#include <math.h>
#include <stdint.h>

#define BATCH 2
#define LSEQ  2048
#define EDIM  1024
#define NLAY  2
#define DI    2048
#define DS    16
#define DC    4
#define DTR   64
#define MROWS (BATCH*LSEQ)          /* 4096 */
#define XW_ROWS (DTR + 2*DS)        /* 96 */

/* ---------------- scratch (static device globals; no allocation) ------- */
__device__ float g_h    [MROWS*EDIM];
__device__ float g_xz   [MROWS*2*DI];
__device__ float g_xconv[MROWS*DI];
__device__ float g_xdbl [MROWS*XW_ROWS];
__device__ float g_delta[MROWS*DI];
__device__ float g_y    [MROWS*DI];
__device__ float g_tmp  [MROWS*EDIM];
/* bf16 split operand buffers */
__device__ __nv_bfloat16 g_ah[MROWS*DI];      /* A-side hi (role rotates)  */
__device__ __nv_bfloat16 g_al[MROWS*DI];      /* A-side lo                 */
__device__ __nv_bfloat16 g_dth[MROWS*DTR];    /* dt_proj A hi (dedicated)  */
__device__ __nv_bfloat16 g_dtl[MROWS*DTR];    /* dt_proj A lo              */
__device__ __nv_bfloat16 g_wh[(2*DI)*EDIM];
__device__ __nv_bfloat16 g_wl[(2*DI)*EDIM];

/* ================= baseline-PTX helpers (sm_80 features only) ========== */
__device__ __forceinline__ uint32_t smem_u32(const void* p) {
    uint32_t a;
    asm("{ .reg .u64 t; cvta.to.shared.u64 t, %1; cvt.u32.u64 %0, t; }"
        : "=r"(a) : "l"(p));
    return a;
}
__device__ __forceinline__ void cp_async16(uint32_t saddr, const void* gaddr) {
    asm volatile("cp.async.cg.shared.global [%0], [%1], 16;"
                 :: "r"(saddr), "l"(gaddr) : "memory");
}
__device__ __forceinline__ void cp_commit() {
    asm volatile("cp.async.commit_group;" ::: "memory");
}
template <int N> __device__ __forceinline__ void cp_wait() {
    asm volatile("cp.async.wait_group %0;" :: "n"(N) : "memory");
}
__device__ __forceinline__ void ldm_x4(uint32_t* d, uint32_t addr) {
    asm volatile("ldmatrix.sync.aligned.m8n8.x4.shared.b16 {%0,%1,%2,%3}, [%4];"
                 : "=r"(d[0]), "=r"(d[1]), "=r"(d[2]), "=r"(d[3]) : "r"(addr));
}
__device__ __forceinline__ void mma16816(float* c, const uint32_t* a, const uint32_t* b) {
    asm volatile("mma.sync.aligned.m16n8k16.row.col.f32.bf16.bf16.f32 "
                 "{%0,%1,%2,%3}, {%4,%5,%6,%7}, {%8,%9}, {%0,%1,%2,%3};"
                 : "+f"(c[0]), "+f"(c[1]), "+f"(c[2]), "+f"(c[3])
                 : "r"(a[0]), "r"(a[1]), "r"(a[2]), "r"(a[3]),
                   "r"(b[0]), "r"(b[1]));
}
__device__ __forceinline__ void bf16_split(float v, __nv_bfloat16* hi, __nv_bfloat16* lo) {
    __nv_bfloat16 h = __float2bfloat16(v);
    *hi = h;
    *lo = __float2bfloat16(v - __bfloat162float(h));
}

/* ================= split-bf16 GEMM via mma.sync ======================== */
/* UNCHANGED from measured R14 kernel (238us in_proj, tensor 70.9%). */
#define STG   65536
#define AH_O  0
#define AL_O  16384
#define WH_O  32768
#define WL_O  49152
#define SMEM_BYTES (2*STG)

__global__ __launch_bounds__(256)
void tc_gemm(const __nv_bfloat16* __restrict__ Ah, const __nv_bfloat16* __restrict__ Al,
             const __nv_bfloat16* __restrict__ Wh, const __nv_bfloat16* __restrict__ Wl,
             float* __restrict__ C, int K, int N, int ldc,
             const float* __restrict__ bias, int mode)
{
    extern __shared__ char dsm[];
    const uint32_t sb  = smem_u32(dsm);
    const int tid    = threadIdx.x;
    const int lane   = tid & 31;
    const int wid    = tid >> 5;
    const int warp_m = wid >> 2;
    const int warp_n = wid & 3;
    const int m0 = blockIdx.y * 128;
    const int n0 = blockIdx.x * 128;

    const int nt = K >> 6;
    auto stage_tile = [&](int t) {
        const int k0   = t << 6;
        const uint32_t s = sb + (t & 1) * STG;
#pragma unroll
        for (int i = tid; i < 1024; i += 256) {
            int r = i >> 3;
            int c = i & 7;
            uint32_t sw = (uint32_t)(r * 128 + ((c ^ (r & 7)) << 4));
            const char* ga  = (const char*)(Ah + (size_t)(m0 + r) * K + k0) + c * 16;
            const char* gal = (const char*)(Al + (size_t)(m0 + r) * K + k0) + c * 16;
            const char* gw  = (const char*)(Wh + (size_t)(n0 + r) * K + k0) + c * 16;
            const char* gwl = (const char*)(Wl + (size_t)(n0 + r) * K + k0) + c * 16;
            cp_async16(s + AH_O + sw, ga);
            cp_async16(s + AL_O + sw, gal);
            cp_async16(s + WH_O + sw, gw);
            cp_async16(s + WL_O + sw, gwl);
        }
        cp_commit();
    };

    float acc[4][4][4];
#pragma unroll
    for (int i = 0; i < 4; i++)
#pragma unroll
        for (int j = 0; j < 4; j++)
#pragma unroll
            for (int e = 0; e < 4; e++) acc[i][j][e] = 0.f;

    stage_tile(0);

    for (int t = 0; t < nt; t++) {
        if (t + 1 < nt) { stage_tile(t + 1); cp_wait<1>(); }
        else            { cp_wait<0>(); }
        __syncthreads();

        const uint32_t s = sb + (t & 1) * STG;

        const int arow = warp_m * 64 + (lane & 15);
        const int ahalf = lane >> 4;
        const int wrow = warp_n * 32 + (lane & 7) + ((lane >> 4) << 3);
        const int whalf = (lane >> 3) & 1;

#pragma unroll
        for (int ks = 0; ks < 4; ks++) {
            uint32_t fah[4][4], fal[4][4], fbh[4][2], fbl[4][2];
#pragma unroll
            for (int mt = 0; mt < 4; mt++) {
                int r = arow + mt * 16;
                int c = ks * 2 + ahalf;
                uint32_t ad = (uint32_t)(r * 128 + ((c ^ (r & 7)) << 4));
                ldm_x4(fah[mt], s + AH_O + ad);
                ldm_x4(fal[mt], s + AL_O + ad);
            }
#pragma unroll
            for (int p = 0; p < 2; p++) {
                int r = wrow + p * 16;
                int c = ks * 2 + whalf;
                uint32_t ad = (uint32_t)(r * 128 + ((c ^ (r & 7)) << 4));
                uint32_t th[4], tl[4];
                ldm_x4(th, s + WH_O + ad);
                ldm_x4(tl, s + WL_O + ad);
                fbh[2*p][0] = th[0]; fbh[2*p][1] = th[1];
                fbh[2*p+1][0] = th[2]; fbh[2*p+1][1] = th[3];
                fbl[2*p][0] = tl[0]; fbl[2*p][1] = tl[1];
                fbl[2*p+1][0] = tl[2]; fbl[2*p+1][1] = tl[3];
            }
#pragma unroll
            for (int mt = 0; mt < 4; mt++)
#pragma unroll
                for (int ntt = 0; ntt < 4; ntt++) {
                    mma16816(acc[mt][ntt], fah[mt], fbh[ntt]);
                    mma16816(acc[mt][ntt], fah[mt], fbl[ntt]);
                    mma16816(acc[mt][ntt], fal[mt], fbh[ntt]);
                }
        }
        __syncthreads();
    }

#pragma unroll
    for (int mt = 0; mt < 4; mt++) {
#pragma unroll
        for (int ntt = 0; ntt < 4; ntt++) {
            int row = m0 + warp_m * 64 + mt * 16 + (lane >> 2);
            int col = n0 + warp_n * 32 + ntt * 8 + ((lane & 3) << 1);
            if (col < N) {
                float v0 = acc[mt][ntt][0], v1 = acc[mt][ntt][1];
                float v2 = acc[mt][ntt][2], v3 = acc[mt][ntt][3];
                if (mode == 1) {
                    float b0 = bias[col], b1 = bias[col + 1];
                    v0 += b0; v1 += b1; v2 += b0; v3 += b1;
                    v0 = (v0 > 20.f) ? v0 : log1pf(__expf(v0));
                    v1 = (v1 > 20.f) ? v1 : log1pf(__expf(v1));
                    v2 = (v2 > 20.f) ? v2 : log1pf(__expf(v2));
                    v3 = (v3 > 20.f) ? v3 : log1pf(__expf(v3));
                }
                *(float2*)(C + (size_t)row * ldc + col)       = make_float2(v0, v1);
                *(float2*)(C + (size_t)(row + 8) * ldc + col) = make_float2(v2, v3);
            }
        }
    }
}

/* ---------------- fp32 -> bf16 hi/lo split (W-side + dt only) ---------- */
__global__ void split_bf16_kernel(const float* __restrict__ src,
                                  __nv_bfloat16* __restrict__ hi,
                                  __nv_bfloat16* __restrict__ lo,
                                  int dst_rows, int cols, int src_rows, int src_stride)
{
    int idx = blockIdx.x * blockDim.x + threadIdx.x;
    if (idx >= dst_rows * cols) return;
    int r = idx / cols;
    int c = idx - r * cols;
    float v = (r < src_rows) ? src[(size_t)r * src_stride + c] : 0.f;
    bf16_split(v, hi + idx, lo + idx);
}

/* ---------------- h = x + pos_embed (+ fused split) -------------------- */
__global__ void addpos_kernel(const float* __restrict__ x,
                              const float* __restrict__ pe)
{
    int idx = blockIdx.x * blockDim.x + threadIdx.x;
    if (idx >= MROWS * EDIM) return;
    int e = idx % EDIM;
    int m = idx / EDIM;
    int l = m % LSEQ;
    float v = x[idx] + pe[l * EDIM + e];
    g_h[idx] = v;
    bf16_split(v, &g_ah[idx], &g_al[idx]);   /* in_proj A split */
}

/* ------- causal depthwise conv1d + bias + silu (+ fused split) --------- */
__global__ void conv_silu_kernel(const float* __restrict__ cw,
                                 const float* __restrict__ cb)
{
    int idx = blockIdx.x * blockDim.x + threadIdx.x;
    if (idx >= MROWS * DI) return;
    int d = idx % DI;
    int m = idx / DI;
    int l = m % LSEQ;
    size_t base = (size_t)(m - l) * (2 * DI) + d;
    float acc = cb[d];
#pragma unroll
    for (int k = 0; k < DC; k++) {
        int ll = l + k - (DC - 1);
        if (ll >= 0)
            acc = fmaf(cw[d * DC + k], g_xz[base + (size_t)ll * (2 * DI)], acc);
    }
    float r = acc / (1.f + __expf(-acc));
    g_xconv[idx] = r;
    bf16_split(r, &g_ah[idx], &g_al[idx]);   /* x_proj A split */
}

/* -------- selective scan, 4-step ILP (+ fused y split) ----------------- */
__global__ __launch_bounds__(256)
void scan_kernel(const float* __restrict__ A_log,
                 const float* __restrict__ D_skip)
{
    int t  = blockIdx.x * blockDim.x + threadIdx.x;
    int ch = t >> 4;
    int n  = t & 15;
    if (ch >= BATCH * DI) return;
    int b = ch / DI;
    int d = ch % DI;

    const float An = -__expf(A_log[d * DS + n]);
    const float Dd = D_skip[d];

    const size_t ybase = (size_t)b * LSEQ * DI + d;
    const float* dp = g_delta + ybase;
    const float* up = g_xconv + ybase;
    const float* zp = g_xz    + (size_t)b * LSEQ * (2 * DI) + DI + d;
    const float* bp = g_xdbl  + (size_t)b * LSEQ * XW_ROWS + DTR + n;
    const float* cp = bp + DS;
    float*               yp  = g_y  + ybase;
    __nv_bfloat16*       yhp = g_ah + ybase;
    __nv_bfloat16*       ylp = g_al + ybase;

    float h = 0.f;
    for (int l = 0; l < LSEQ; l += 4) {
        float dl[4], ul[4], bn[4], cn[4];
#pragma unroll
        for (int i = 0; i < 4; i++) {
            dl[i] = dp[(size_t)(l + i) * DI];
            ul[i] = up[(size_t)(l + i) * DI];
            bn[i] = bp[(l + i) * XW_ROWS];
            cn[i] = cp[(l + i) * XW_ROWS];
        }
        float e[4], w[4];
#pragma unroll
        for (int i = 0; i < 4; i++) {
            e[i] = __expf(dl[i] * An);
            w[i] = dl[i] * ul[i] * bn[i];
        }
        float p[4];
#pragma unroll
        for (int i = 0; i < 4; i++) {        /* 4-cyc FMA chain only */
            h = fmaf(e[i], h, w[i]);
            p[i] = h * cn[i];
        }
#pragma unroll
        for (int o = 1; o <= 8; o <<= 1)     /* 4 pipelined shfl chains */
#pragma unroll
            for (int i = 0; i < 4; i++)
                p[i] += __shfl_xor_sync(0xffffffffu, p[i], o);

        if (n == 0) {
#pragma unroll
            for (int i = 0; i < 4; i++) {
                float zl = zp[(size_t)(l + i) * (2 * DI)];
                float yv = (p[i] + ul[i] * Dd) * (zl / (1.f + __expf(-zl)));
                size_t yi = (size_t)(l + i) * DI;
                yp[yi] = yv;
                bf16_split(yv, yhp + yi, ylp + yi);   /* out_proj A split */
            }
        }
    }
}

/* -------- rmsnorm(t + hin) * w (+ optional fused split) ---------------- */
__global__ __launch_bounds__(256)
void rmsnorm_kernel(const float* __restrict__ t, const float* __restrict__ hin,
                    const float* __restrict__ w, float* __restrict__ out,
                    int write_split)
{
    __shared__ float buf[EDIM];
    __shared__ float red[8];
    int m   = blockIdx.x;
    int tid = threadIdx.x;
    float ss = 0.f;
    for (int e = tid; e < EDIM; e += 256) {
        float v = t[(size_t)m * EDIM + e] + hin[(size_t)m * EDIM + e];
        buf[e] = v;
        ss += v * v;
    }
#pragma unroll
    for (int o = 16; o; o >>= 1) ss += __shfl_xor_sync(0xffffffffu, ss, o);
    if ((tid & 31) == 0) red[tid >> 5] = ss;
    __syncthreads();
    if (tid < 32) {
        float v = (tid < 8) ? red[tid] : 0.f;
#pragma unroll
        for (int o = 4; o; o >>= 1) v += __shfl_xor_sync(0xffffffffu, v, o);
        if (tid == 0) red[0] = v;
    }
    __syncthreads();
    float scale = rsqrtf(red[0] / EDIM + 1e-6f);
    for (int e = tid; e < EDIM; e += 256) {
        size_t idx = (size_t)m * EDIM + e;
        float v = buf[e] * scale * w[e];
        out[idx] = v;
        if (write_split)
            bf16_split(v, &g_ah[idx], &g_al[idx]);  /* next in_proj A split */
    }
}

/* ---------------- host driver ------------------------------------------ */
static inline void split_launch(const float* src, __nv_bfloat16* hi, __nv_bfloat16* lo,
                                int dst_rows, int cols, int src_rows, int src_stride)
{
    int n = dst_rows * cols;
    split_bf16_kernel<<<(n + 255) / 256, 256>>>(src, hi, lo, dst_rows, cols,
                                                src_rows, src_stride);
}

extern "C" void kernel_launch(void* const* d_in, const int* in_sizes, int n_in,
                              void* d_out, int out_size)
{
    const float* x    = (const float*)d_in[0];
    const float* pe   = (const float*)d_in[1];
    const float* inw  = (const float*)d_in[2];
    const float* cw   = (const float*)d_in[3];
    const float* cb   = (const float*)d_in[4];
    const float* xw   = (const float*)d_in[5];
    const float* dtw  = (const float*)d_in[6];
    const float* dtb  = (const float*)d_in[7];
    const float* alog = (const float*)d_in[8];
    const float* dsk  = (const float*)d_in[9];
    const float* ow   = (const float*)d_in[10];
    const float* nw   = (const float*)d_in[11];
    float* out        = (float*)d_out;

    cudaFuncSetAttribute(tc_gemm, cudaFuncAttributeMaxDynamicSharedMemorySize,
                         SMEM_BYTES);

    float *ph, *pxz, *pxconv, *pxdbl, *pdelta, *py, *ptmp;
    __nv_bfloat16 *pah, *pal, *pdth, *pdtl, *pwh, *pwl;
    cudaGetSymbolAddress((void**)&ph,     g_h);
    cudaGetSymbolAddress((void**)&pxz,    g_xz);
    cudaGetSymbolAddress((void**)&pxconv, g_xconv);
    cudaGetSymbolAddress((void**)&pxdbl,  g_xdbl);
    cudaGetSymbolAddress((void**)&pdelta, g_delta);
    cudaGetSymbolAddress((void**)&py,     g_y);
    cudaGetSymbolAddress((void**)&ptmp,   g_tmp);
    cudaGetSymbolAddress((void**)&pah,    g_ah);
    cudaGetSymbolAddress((void**)&pal,    g_al);
    cudaGetSymbolAddress((void**)&pdth,   g_dth);
    cudaGetSymbolAddress((void**)&pdtl,   g_dtl);
    cudaGetSymbolAddress((void**)&pwh,    g_wh);
    cudaGetSymbolAddress((void**)&pwl,    g_wl);

    /* h = x + pos (also produces in_proj A split for layer 0) */
    addpos_kernel<<<(MROWS * EDIM + 255) / 256, 256>>>(x, pe);

    for (int layer = 0; layer < NLAY; layer++) {
        const float* inw_l = inw  + (size_t)layer * (2 * DI) * EDIM;
        const float* cw_l  = cw   + (size_t)layer * DI * DC;
        const float* cb_l  = cb   + (size_t)layer * DI;
        const float* xw_l  = xw   + (size_t)layer * XW_ROWS * DI;
        const float* dtw_l = dtw  + (size_t)layer * DI * DTR;
        const float* dtb_l = dtb  + (size_t)layer * DI;
        const float* al_l  = alog + (size_t)layer * DI * DS;
        const float* ds_l  = dsk  + (size_t)layer * DI;
        const float* ow_l  = ow   + (size_t)layer * EDIM * DI;
        const float* nw_l  = nw   + (size_t)layer * EDIM;

        /* ---- in_proj: (4096 x 4096), K=1024 (A split pre-fused) ---- */
        split_launch(inw_l, pwh, pwl, 2 * DI, EDIM, 2 * DI, EDIM);
        tc_gemm<<<dim3((2 * DI) / 128, MROWS / 128), 256, SMEM_BYTES>>>(
            pah, pal, pwh, pwl, pxz, EDIM, 2 * DI, 2 * DI, nullptr, 0);

        /* conv + silu, fused xconv split (overwrites g_ah/g_al AFTER in_proj) */
        conv_silu_kernel<<<(MROWS * DI + 255) / 256, 256>>>(cw_l, cb_l);

        /* ---- x_proj: (4096 x 96), K=2048, weight padded to 128 rows ---- */
        split_launch(xw_l, pwh, pwl, 128, DI, XW_ROWS, DI);
        tc_gemm<<<dim3(1, MROWS / 128), 256, SMEM_BYTES>>>(
            pah, pal, pwh, pwl, pxdbl, DI, XW_ROWS, XW_ROWS, nullptr, 0);

        /* ---- dt_proj: (4096 x 2048), K=64, fused softplus+bias ---- */
        split_launch(pxdbl, pdth, pdtl, MROWS, DTR, MROWS, XW_ROWS);
        split_launch(dtw_l, pwh, pwl, DI, DTR, DI, DTR);
        tc_gemm<<<dim3(DI / 128, MROWS / 128), 256, SMEM_BYTES>>>(
            pdth, pdtl, pwh, pwl, pdelta, DTR, DI, DI, dtb_l, 1);

        /* ---- selective scan + gate, fused y split (after x_proj done) ---- */
        scan_kernel<<<(BATCH * DI * 16) / 256, 256>>>(al_l, ds_l);

        /* ---- out_proj: (4096 x 1024), K=2048 ---- */
        split_launch(ow_l, pwh, pwl, EDIM, DI, EDIM, DI);
        tc_gemm<<<dim3(EDIM / 128, MROWS / 128), 256, SMEM_BYTES>>>(
            pah, pal, pwh, pwl, ptmp, DI, EDIM, EDIM, nullptr, 0);

        /* ---- h = rmsnorm(out + h) * w; fused split for next layer ---- */
        rmsnorm_kernel<<<MROWS, 256>>>(
            ptmp, ph, nw_l, (layer == NLAY - 1) ? out : ph,
            (layer < NLAY - 1) ? 1 : 0);
    }
}